// round 15
// baseline (speedup 1.0000x reference)
#include <cuda_runtime.h>
#include <cuda_fp16.h>
#include <cstdint>

#define BB   32
#define NN   16384
#define DD   128
#define IDM  64
#define NCLS 10

// ---------------------------------------------------------------------------
// Scratch (device globals — no allocation allowed)
// ---------------------------------------------------------------------------
__device__ float g_scores[BB * NN];
__device__ float g_u[BB * DD];
__device__ float g_C[BB];
__device__ float g_tau[BB];
__device__ float g_gbar[BB * DD];
__device__ __align__(16) unsigned long long g_wfrag[2048];
__device__ float g_M1[DD * DD];
__device__ float g_A2t[DD * DD];
__device__ float g_v[DD];
__device__ float g_cq[DD];
__device__ int   g_cntB[BB];   // zero-init; reset by last user each replay
__device__ int   g_cntC[BB];

__device__ __forceinline__ float gelu_exact(float x) {
    return 0.5f * x * (1.0f + erff(x * 0.7071067811865475f));
}

// gelu_tanh(x)*u = x*u*sigmoid(2y): ex2 + rcp form
__device__ __forceinline__ float gdot(float x, float u) {
    float x2 = x * x;
    float ys = x * fmaf(-0.10294322f, x2, -2.30220798f);
    float e;
    asm("ex2.approx.f32 %0, %1;" : "=f"(e) : "f"(ys));
    float d = e + 1.0f;
    float r;
    asm("rcp.approx.f32 %0, %1;" : "=f"(r) : "f"(d));
    return (x * u) * r;
}

__device__ __forceinline__ void mma16816(float* c, const uint32_t* a,
                                         uint32_t b0, uint32_t b1) {
    asm volatile(
        "mma.sync.aligned.m16n8k16.row.col.f32.f16.f16.f32 "
        "{%0,%1,%2,%3}, {%4,%5,%6,%7}, {%8,%9}, {%0,%1,%2,%3};"
        : "+f"(c[0]), "+f"(c[1]), "+f"(c[2]), "+f"(c[3])
        : "r"(a[0]), "r"(a[1]), "r"(a[2]), "r"(a[3]), "r"(b0), "r"(b1));
}

__device__ __forceinline__ uint32_t pack_h2(float lo, float hi) {
    __half2 h = __floats2half2_rn(lo, hi);
    return *reinterpret_cast<uint32_t*>(&h);
}

// ---------------------------------------------------------------------------
// k1a: independent precomputes. 274 blocks x 128 threads.
// ---------------------------------------------------------------------------
__global__ void __launch_bounds__(128) k1a(
    const float* __restrict__ wx1,
    const float* __restrict__ wq2, const float* __restrict__ bq2,
    const float* __restrict__ wqp, const float* __restrict__ bqp,
    const float* __restrict__ wkp, const float* __restrict__ bkp,
    const float* __restrict__ wx2, const float* __restrict__ bx2)
{
    const int bid = blockIdx.x;
    const int t   = threadIdx.x;

    if (bid < 128) {
        const int k = bid;
        float a0 = 0.f, a1 = 0.f;
#pragma unroll 8
        for (int p = 0; p < DD; p += 2) {
            a0 += wq2[k * DD + p + 0] * wqp[(p + 0) * DD + t];
            a1 += wq2[k * DD + p + 1] * wqp[(p + 1) * DD + t];
        }
        g_M1[k * DD + t] = a0 + a1;
    } else if (bid < 256) {
        const int i = bid - 128;
        float a0 = 0.f, a1 = 0.f;
#pragma unroll 8
        for (int j = 0; j < DD; j += 2) {
            a0 += wx2[i * DD + j + 0] * wkp[(j + 0) * DD + t];
            a1 += wx2[i * DD + j + 1] * wkp[(j + 1) * DD + t];
        }
        g_A2t[t * DD + i] = a0 + a1;
    } else if (bid < 272) {
        int s = (bid - 256) * 128 + t;
        int l  = s & 31;
        int ks = (s >> 5) & 3;
        int nt = s >> 7;
        int n  = nt * 8 + (l >> 2);
        int k0 = ks * 16 + (l & 3) * 2;
        float w0 = wx1[(k0 + 0) * DD + n];
        float w1 = wx1[(k0 + 1) * DD + n];
        float w8 = wx1[(k0 + 8) * DD + n];
        float w9 = wx1[(k0 + 9) * DD + n];
        g_wfrag[s] = (unsigned long long)pack_h2(w0, w1)
                   | ((unsigned long long)pack_h2(w8, w9) << 32);
    } else if (bid == 272) {
        float a = 0.f;
#pragma unroll 8
        for (int i = 0; i < DD; i++) a += bx2[i] * wkp[i * DD + t];
        g_v[t] = a + bkp[t];
    } else {
        float a = 0.f;
#pragma unroll 8
        for (int p = 0; p < DD; p++) a += bq2[p] * wqp[p * DD + t];
        g_cq[t] = a + bqp[t];
    }
}

// ---------------------------------------------------------------------------
// k1c: per-batch finals. 32 blocks x 128.
// ---------------------------------------------------------------------------
__global__ void __launch_bounds__(128) k1c(
    const float* __restrict__ xq_all,
    const float* __restrict__ wq1, const float* __restrict__ bq1)
{
    __shared__ float sg[DD];
    __shared__ float qm[DD];
    __shared__ float red[4];
    const int b = blockIdx.x;
    const int t = threadIdx.x;

    sg[t] = gelu_exact(xq_all[b] * wq1[t] + bq1[t]);
    __syncthreads();

    {
        float a0 = 0.f, a1 = 0.f;
#pragma unroll 8
        for (int k = 0; k < DD; k += 2) {
            a0 += sg[k + 0] * g_M1[(k + 0) * DD + t];
            a1 += sg[k + 1] * g_M1[(k + 1) * DD + t];
        }
        qm[t] = a0 + a1 + g_cq[t];
    }
    __syncthreads();

    {
        float a0 = 0.f, a1 = 0.f;
#pragma unroll 8
        for (int m = 0; m < DD; m += 2) {
            a0 += g_A2t[(m + 0) * DD + t] * qm[m + 0];
            a1 += g_A2t[(m + 1) * DD + t] * qm[m + 1];
        }
        g_u[b * DD + t] = a0 + a1;
    }

    float p = qm[t] * g_v[t];
#pragma unroll
    for (int o = 16; o > 0; o >>= 1) p += __shfl_xor_sync(0xffffffffu, p, o);
    if ((t & 31) == 0) red[t >> 5] = p;
    __syncthreads();
    if (t == 0) g_C[b] = red[0] + red[1] + red[2] + red[3];
}

// ---------------------------------------------------------------------------
// k2: scores (HMMA) + FUSED per-batch tau (last arriving block of each batch).
// Grid (NN/256, BB), 256 threads (8 warps).
// ---------------------------------------------------------------------------
static constexpr int S_B   = 0;         // 16384 bytes
static constexpr int S_US  = 16384;
static constexpr int S_BXS = S_US + 512;
static constexpr int S_TOT = S_BXS + 512;

#define MICH_ROUNDS 20

__global__ void __launch_bounds__(256) k2_scores_hmma(
    const float* __restrict__ x_items,
    const float* __restrict__ bx1)
{
    extern __shared__ char smem[];
    const int tid = threadIdx.x;
    const int wid = tid >> 5;
    const int lid = tid & 31;
    const int qr  = lid >> 2;
    const int qc  = lid & 3;
    const int b   = blockIdx.y;
    const int tile0 = blockIdx.x * 256;

    float* us  = reinterpret_cast<float*>(smem + S_US);
    float* bxs = reinterpret_cast<float*>(smem + S_BXS);
    if (tid < DD) {
        us[tid]  = g_u[b * DD + tid];
        bxs[tid] = bx1[tid];
    }
    const float Cs = g_C[b];

    {
        const uint4* gf = reinterpret_cast<const uint4*>(g_wfrag);
        uint4* bs = reinterpret_cast<uint4*>(smem + S_B);
#pragma unroll
        for (int j = 0; j < 4; j++) bs[tid + j * 256] = gf[tid + j * 256];
    }

    uint32_t A[2][4][4];
    {
        const float* xb = x_items + ((size_t)b * NN + (size_t)tile0) * IDM;
#pragma unroll
        for (int mt = 0; mt < 2; mt++) {
            int r0 = wid * 32 + mt * 16 + qr;
#pragma unroll
            for (int ks = 0; ks < 4; ks++) {
                int k0 = ks * 16 + qc * 2;
                float2 v00 = *reinterpret_cast<const float2*>(xb + (size_t)r0 * IDM + k0);
                float2 v10 = *reinterpret_cast<const float2*>(xb + (size_t)(r0 + 8) * IDM + k0);
                float2 v01 = *reinterpret_cast<const float2*>(xb + (size_t)r0 * IDM + k0 + 8);
                float2 v11 = *reinterpret_cast<const float2*>(xb + (size_t)(r0 + 8) * IDM + k0 + 8);
                A[mt][ks][0] = pack_h2(v00.x, v00.y);
                A[mt][ks][1] = pack_h2(v10.x, v10.y);
                A[mt][ks][2] = pack_h2(v01.x, v01.y);
                A[mt][ks][3] = pack_h2(v11.x, v11.y);
            }
        }
    }
    __syncthreads();

    float sc[2][2] = {{0.f, 0.f}, {0.f, 0.f}};
#pragma unroll 1
    for (int nt = 0; nt < 16; nt++) {
        int n0 = nt * 8 + qc * 2;
        float2 bias = *reinterpret_cast<const float2*>(&bxs[n0]);
        float2 uu   = *reinterpret_cast<const float2*>(&us[n0]);
        float c0[4] = {bias.x, bias.y, bias.x, bias.y};
        float c1[4] = {bias.x, bias.y, bias.x, bias.y};
#pragma unroll
        for (int ks = 0; ks < 4; ks++) {
            unsigned long long bb = *reinterpret_cast<const unsigned long long*>(
                smem + S_B + (((nt * 4 + ks) * 32) + lid) * 8);
            uint32_t b0 = (uint32_t)bb;
            uint32_t b1 = (uint32_t)(bb >> 32);
            mma16816(c0, A[0][ks], b0, b1);
            mma16816(c1, A[1][ks], b0, b1);
        }
        sc[0][0] += gdot(c0[0], uu.x) + gdot(c0[1], uu.y);
        sc[0][1] += gdot(c0[2], uu.x) + gdot(c0[3], uu.y);
        sc[1][0] += gdot(c1[0], uu.x) + gdot(c1[1], uu.y);
        sc[1][1] += gdot(c1[2], uu.x) + gdot(c1[3], uu.y);
    }

#pragma unroll
    for (int mt = 0; mt < 2; mt++) {
#pragma unroll
        for (int h = 0; h < 2; h++) {
            float v = sc[mt][h];
            v += __shfl_xor_sync(0xffffffffu, v, 1);
            v += __shfl_xor_sync(0xffffffffu, v, 2);
            sc[mt][h] = v;
        }
    }
    if (qc == 0) {
#pragma unroll
        for (int mt = 0; mt < 2; mt++) {
#pragma unroll
            for (int h = 0; h < 2; h++) {
                int item = tile0 + wid * 32 + mt * 16 + h * 8 + qr;
                g_scores[b * NN + item] =
                    0.08838834764831845f * (sc[mt][h] + Cs);
            }
        }
    }

    // ---- fused tau: last arriving block of this batch computes tau_b ----
    __shared__ int isLast;
    __shared__ float sS[8];
    __shared__ float sK[8];
    __shared__ float bc[1];

    __threadfence();
    __syncthreads();
    if (tid == 0) {
        int old = atomicAdd(&g_cntB[b], 1);
        int last = (old == gridDim.x - 1);
        if (last) g_cntB[b] = 0;       // reset for next graph replay
        isLast = last;
    }
    __syncthreads();
    if (!isLast) return;
    __threadfence();

    // zero gbar for this batch
    if (tid < DD) g_gbar[b * DD + tid] = 0.f;

    const float* scb = g_scores + b * NN;

    // block max (256 threads, 64 values each)
    float m = -3.0e38f;
#pragma unroll 8
    for (int j = 0; j < NN / 256; j++) m = fmaxf(m, __ldg(scb + tid + j * 256));
#pragma unroll
    for (int o = 16; o > 0; o >>= 1) m = fmaxf(m, __shfl_xor_sync(0xffffffffu, m, o));
    if (lid == 0) sS[wid] = m;
    __syncthreads();
    if (wid == 0) {
        float v = (lid < 8) ? sS[lid] : -3.0e38f;
#pragma unroll
        for (int o = 4; o > 0; o >>= 1) v = fmaxf(v, __shfl_xor_sync(0xffffffffu, v, o));
        if (lid == 0) bc[0] = v;
    }
    __syncthreads();
    float tau = bc[0] - 1.0f;

#pragma unroll 1
    for (int r = 0; r < MICH_ROUNDS; r++) {
        float s = 0.f, c = 0.f;
#pragma unroll 8
        for (int j = 0; j < NN / 256; j++) {
            float zz = __ldg(scb + tid + j * 256);
            if (zz > tau) { s += zz; c += 1.f; }
        }
#pragma unroll
        for (int o = 16; o > 0; o >>= 1) {
            s += __shfl_xor_sync(0xffffffffu, s, o);
            c += __shfl_xor_sync(0xffffffffu, c, o);
        }
        if (lid == 0) { sS[wid] = s; sK[wid] = c; }
        __syncthreads();
        if (wid == 0) {
            float s2 = (lid < 8) ? sS[lid] : 0.f;
            float c2 = (lid < 8) ? sK[lid] : 0.f;
#pragma unroll
            for (int o = 4; o > 0; o >>= 1) {
                s2 += __shfl_xor_sync(0xffffffffu, s2, o);
                c2 += __shfl_xor_sync(0xffffffffu, c2, o);
            }
            if (lid == 0) bc[0] = (s2 - 1.0f) / c2;
        }
        __syncthreads();
        float tn = bc[0];
        if (tn <= tau) break;
        tau = tn;
    }

    if (tid == 0) g_tau[b] = tau;
}

// ---------------------------------------------------------------------------
// k3: sparse accumulation + FUSED head MLP (last arriving block per batch).
// Grid (32, 32) x 256 threads.
// ---------------------------------------------------------------------------
__global__ void __launch_bounds__(256) k3_accum_head(
    const float* __restrict__ x_items,
    const float* __restrict__ wx1, const float* __restrict__ bx1,
    const float* __restrict__ wx2, const float* __restrict__ bx2,
    const float* __restrict__ wvp, const float* __restrict__ bvp,
    const float* __restrict__ wp1, const float* __restrict__ bp1,
    const float* __restrict__ wp2, const float* __restrict__ bp2,
    float* __restrict__ out)
{
    __shared__ float accg[DD];
    __shared__ float buf1[DD];
    __shared__ float buf2[DD];
    const int tid  = threadIdx.x;
    const int lane = tid & 31;
    const int wid  = tid >> 5;
    const int b    = blockIdx.y;
    const int base = blockIdx.x * 512 + wid * 64;

    if (tid < DD) accg[tid] = 0.f;
    __syncthreads();

    const float tau = g_tau[b];
    const float* sc = g_scores + b * NN;

#pragma unroll 1
    for (int win = 0; win < 2; win++) {
        int idx0 = base + win * 32;
        float zz = sc[idx0 + lane];
        unsigned msk = __ballot_sync(0xffffffffu, zz > tau);
        while (msk) {
            int jb = __ffs(msk) - 1;
            msk &= msk - 1;
            float w = __shfl_sync(0xffffffffu, zz, jb) - tau;
            int item = idx0 + jb;
            const float* xr = x_items + ((size_t)b * NN + (size_t)item) * IDM;
            float x0 = xr[2 * lane], x1 = xr[2 * lane + 1];
            float a0 = bx1[lane];
            float a1 = bx1[lane + 32];
            float a2 = bx1[lane + 64];
            float a3 = bx1[lane + 96];
#pragma unroll
            for (int k = 0; k < IDM; k++) {
                float xv = __shfl_sync(0xffffffffu, (k & 1) ? x1 : x0, k >> 1);
                a0 += xv * wx1[k * DD + lane];
                a1 += xv * wx1[k * DD + lane + 32];
                a2 += xv * wx1[k * DD + lane + 64];
                a3 += xv * wx1[k * DD + lane + 96];
            }
            atomicAdd(&accg[lane],      w * gelu_exact(a0));
            atomicAdd(&accg[lane + 32], w * gelu_exact(a1));
            atomicAdd(&accg[lane + 64], w * gelu_exact(a2));
            atomicAdd(&accg[lane + 96], w * gelu_exact(a3));
        }
    }
    __syncthreads();
    if (tid < DD) {
        float v = accg[tid];
        if (v != 0.f) atomicAdd(&g_gbar[b * DD + tid], v);
    }

    // ---- fused head: last arriving block of this batch ----
    __shared__ int isLast;
    __threadfence();
    __syncthreads();
    if (tid == 0) {
        int old = atomicAdd(&g_cntC[b], 1);
        int last = (old == gridDim.x - 1);
        if (last) g_cntC[b] = 0;
        isLast = last;
    }
    __syncthreads();
    if (!isLast) return;
    __threadfence();

    if (tid < DD) accg[tid] = g_gbar[b * DD + tid];
    __syncthreads();

    if (tid < DD) {
        float a0 = 0.f, a1 = 0.f, a2 = 0.f, a3 = 0.f;
#pragma unroll 8
        for (int k = 0; k < DD; k += 4) {
            a0 += accg[k + 0] * wx2[(k + 0) * DD + tid];
            a1 += accg[k + 1] * wx2[(k + 1) * DD + tid];
            a2 += accg[k + 2] * wx2[(k + 2) * DD + tid];
            a3 += accg[k + 3] * wx2[(k + 3) * DD + tid];
        }
        buf1[tid] = (a0 + a1) + (a2 + a3) + bx2[tid];
    }
    __syncthreads();
    if (tid < DD) {
        float a0 = 0.f, a1 = 0.f, a2 = 0.f, a3 = 0.f;
#pragma unroll 8
        for (int k = 0; k < DD; k += 4) {
            a0 += buf1[k + 0] * wvp[(k + 0) * DD + tid];
            a1 += buf1[k + 1] * wvp[(k + 1) * DD + tid];
            a2 += buf1[k + 2] * wvp[(k + 2) * DD + tid];
            a3 += buf1[k + 3] * wvp[(k + 3) * DD + tid];
        }
        buf2[tid] = (a0 + a1) + (a2 + a3) + bvp[tid];
    }
    __syncthreads();
    if (tid < DD) {
        float a0 = 0.f, a1 = 0.f, a2 = 0.f, a3 = 0.f;
#pragma unroll 8
        for (int k = 0; k < DD; k += 4) {
            a0 += buf2[k + 0] * wp1[(k + 0) * DD + tid];
            a1 += buf2[k + 1] * wp1[(k + 1) * DD + tid];
            a2 += buf2[k + 2] * wp1[(k + 2) * DD + tid];
            a3 += buf2[k + 3] * wp1[(k + 3) * DD + tid];
        }
        buf1[tid] = gelu_exact((a0 + a1) + (a2 + a3) + bp1[tid]);
    }
    __syncthreads();
    if (tid < NCLS) {
        float o = bp2[tid];
#pragma unroll 8
        for (int k = 0; k < DD; k++) o += buf1[k] * wp2[k * NCLS + tid];
        out[b * NCLS + tid] = o;
    }
}

// ---------------------------------------------------------------------------
extern "C" void kernel_launch(void* const* d_in, const int* in_sizes, int n_in,
                              void* d_out, int out_size)
{
    const float* x_items = (const float*)d_in[0];
    const float* x_query = (const float*)d_in[1];
    const float* wx1 = (const float*)d_in[2];
    const float* bx1 = (const float*)d_in[3];
    const float* wx2 = (const float*)d_in[4];
    const float* bx2 = (const float*)d_in[5];
    const float* wq1 = (const float*)d_in[6];
    const float* bq1 = (const float*)d_in[7];
    const float* wq2 = (const float*)d_in[8];
    const float* bq2 = (const float*)d_in[9];
    const float* wqp = (const float*)d_in[10];
    const float* bqp = (const float*)d_in[11];
    const float* wkp = (const float*)d_in[12];
    const float* bkp = (const float*)d_in[13];
    const float* wvp = (const float*)d_in[14];
    const float* bvp = (const float*)d_in[15];
    const float* wp1 = (const float*)d_in[16];
    const float* bp1 = (const float*)d_in[17];
    const float* wp2 = (const float*)d_in[18];
    const float* bp2 = (const float*)d_in[19];
    float* out = (float*)d_out;

    cudaFuncSetAttribute(k2_scores_hmma,
                         cudaFuncAttributeMaxDynamicSharedMemorySize, S_TOT);

    k1a<<<274, 128>>>(wx1, wq2, bq2, wqp, bqp, wkp, bkp, wx2, bx2);
    k1c<<<BB, 128>>>(x_query, wq1, bq1);

    dim3 g2(NN / 256, BB);
    k2_scores_hmma<<<g2, 256, S_TOT>>>(x_items, bx1);

    dim3 g3(32, BB);
    k3_accum_head<<<g3, 256>>>(x_items, wx1, bx1, wx2, bx2,
                               wvp, bvp, wp1, bp1, wp2, bp2, out);
}

// round 16
// speedup vs baseline: 1.4682x; 1.4682x over previous
#include <cuda_runtime.h>
#include <cuda_fp16.h>
#include <cstdint>

#define BB   32
#define NN   16384
#define DD   128
#define IDM  64
#define NCLS 10

// ---------------------------------------------------------------------------
// Scratch (device globals — no allocation allowed)
// ---------------------------------------------------------------------------
__device__ float g_scores[BB * NN];
__device__ float g_u[BB * DD];
__device__ float g_C[BB];
__device__ float g_tau[BB];
__device__ float g_gbar[BB * DD];
__device__ __align__(16) unsigned long long g_wfrag[2048];
__device__ float g_M1[DD * DD];
__device__ float g_A2t[DD * DD];
__device__ float g_v[DD];
__device__ float g_cq[DD];
__device__ int   g_cntC[BB];   // zero-init; last user resets each replay

__device__ __forceinline__ float gelu_exact(float x) {
    return 0.5f * x * (1.0f + erff(x * 0.7071067811865475f));
}

// gelu_tanh(x)*u = x*u*sigmoid(2y): ex2 + rcp form
__device__ __forceinline__ float gdot(float x, float u) {
    float x2 = x * x;
    float ys = x * fmaf(-0.10294322f, x2, -2.30220798f);
    float e;
    asm("ex2.approx.f32 %0, %1;" : "=f"(e) : "f"(ys));
    float d = e + 1.0f;
    float r;
    asm("rcp.approx.f32 %0, %1;" : "=f"(r) : "f"(d));
    return (x * u) * r;
}

__device__ __forceinline__ void mma16816(float* c, const uint32_t* a,
                                         uint32_t b0, uint32_t b1) {
    asm volatile(
        "mma.sync.aligned.m16n8k16.row.col.f32.f16.f16.f32 "
        "{%0,%1,%2,%3}, {%4,%5,%6,%7}, {%8,%9}, {%0,%1,%2,%3};"
        : "+f"(c[0]), "+f"(c[1]), "+f"(c[2]), "+f"(c[3])
        : "r"(a[0]), "r"(a[1]), "r"(a[2]), "r"(a[3]), "r"(b0), "r"(b1));
}

__device__ __forceinline__ uint32_t pack_h2(float lo, float hi) {
    __half2 h = __floats2half2_rn(lo, hi);
    return *reinterpret_cast<uint32_t*>(&h);
}

// ---------------------------------------------------------------------------
// k1a: independent precomputes. 274 blocks x 128 threads.
// ---------------------------------------------------------------------------
__global__ void __launch_bounds__(128) k1a(
    const float* __restrict__ wx1,
    const float* __restrict__ wq2, const float* __restrict__ bq2,
    const float* __restrict__ wqp, const float* __restrict__ bqp,
    const float* __restrict__ wkp, const float* __restrict__ bkp,
    const float* __restrict__ wx2, const float* __restrict__ bx2)
{
    const int bid = blockIdx.x;
    const int t   = threadIdx.x;

    if (bid < 128) {
        const int k = bid;
        float a0 = 0.f, a1 = 0.f;
#pragma unroll 8
        for (int p = 0; p < DD; p += 2) {
            a0 += wq2[k * DD + p + 0] * wqp[(p + 0) * DD + t];
            a1 += wq2[k * DD + p + 1] * wqp[(p + 1) * DD + t];
        }
        g_M1[k * DD + t] = a0 + a1;
    } else if (bid < 256) {
        const int i = bid - 128;
        float a0 = 0.f, a1 = 0.f;
#pragma unroll 8
        for (int j = 0; j < DD; j += 2) {
            a0 += wx2[i * DD + j + 0] * wkp[(j + 0) * DD + t];
            a1 += wx2[i * DD + j + 1] * wkp[(j + 1) * DD + t];
        }
        g_A2t[t * DD + i] = a0 + a1;
    } else if (bid < 272) {
        int s = (bid - 256) * 128 + t;
        int l  = s & 31;
        int ks = (s >> 5) & 3;
        int nt = s >> 7;
        int n  = nt * 8 + (l >> 2);
        int k0 = ks * 16 + (l & 3) * 2;
        float w0 = wx1[(k0 + 0) * DD + n];
        float w1 = wx1[(k0 + 1) * DD + n];
        float w8 = wx1[(k0 + 8) * DD + n];
        float w9 = wx1[(k0 + 9) * DD + n];
        g_wfrag[s] = (unsigned long long)pack_h2(w0, w1)
                   | ((unsigned long long)pack_h2(w8, w9) << 32);
    } else if (bid == 272) {
        float a = 0.f;
#pragma unroll 8
        for (int i = 0; i < DD; i++) a += bx2[i] * wkp[i * DD + t];
        g_v[t] = a + bkp[t];
    } else {
        float a = 0.f;
#pragma unroll 8
        for (int p = 0; p < DD; p++) a += bq2[p] * wqp[p * DD + t];
        g_cq[t] = a + bqp[t];
    }
}

// ---------------------------------------------------------------------------
// k1c: per-batch finals. 32 blocks x 128.
// ---------------------------------------------------------------------------
__global__ void __launch_bounds__(128) k1c(
    const float* __restrict__ xq_all,
    const float* __restrict__ wq1, const float* __restrict__ bq1)
{
    __shared__ float sg[DD];
    __shared__ float qm[DD];
    __shared__ float red[4];
    const int b = blockIdx.x;
    const int t = threadIdx.x;

    sg[t] = gelu_exact(xq_all[b] * wq1[t] + bq1[t]);
    __syncthreads();

    {
        float a0 = 0.f, a1 = 0.f;
#pragma unroll 8
        for (int k = 0; k < DD; k += 2) {
            a0 += sg[k + 0] * g_M1[(k + 0) * DD + t];
            a1 += sg[k + 1] * g_M1[(k + 1) * DD + t];
        }
        qm[t] = a0 + a1 + g_cq[t];
    }
    __syncthreads();

    {
        float a0 = 0.f, a1 = 0.f;
#pragma unroll 8
        for (int m = 0; m < DD; m += 2) {
            a0 += g_A2t[(m + 0) * DD + t] * qm[m + 0];
            a1 += g_A2t[(m + 1) * DD + t] * qm[m + 1];
        }
        g_u[b * DD + t] = a0 + a1;
    }

    float p = qm[t] * g_v[t];
#pragma unroll
    for (int o = 16; o > 0; o >>= 1) p += __shfl_xor_sync(0xffffffffu, p, o);
    if ((t & 31) == 0) red[t >> 5] = p;
    __syncthreads();
    if (t == 0) g_C[b] = red[0] + red[1] + red[2] + red[3];
}

// ---------------------------------------------------------------------------
// k2: scores via single-product fp16 HMMA; gelu*u epilogue.
// Grid (NN/256, BB), 256 threads (8 warps).
// ---------------------------------------------------------------------------
static constexpr int S_B   = 0;         // 16384 bytes
static constexpr int S_US  = 16384;
static constexpr int S_BXS = S_US + 512;
static constexpr int S_TOT = S_BXS + 512;

__global__ void __launch_bounds__(256) k2_scores_hmma(
    const float* __restrict__ x_items,
    const float* __restrict__ bx1)
{
    extern __shared__ char smem[];
    const int tid = threadIdx.x;
    const int wid = tid >> 5;
    const int lid = tid & 31;
    const int qr  = lid >> 2;
    const int qc  = lid & 3;
    const int b   = blockIdx.y;
    const int tile0 = blockIdx.x * 256;

    float* us  = reinterpret_cast<float*>(smem + S_US);
    float* bxs = reinterpret_cast<float*>(smem + S_BXS);
    if (tid < DD) {
        us[tid]  = g_u[b * DD + tid];
        bxs[tid] = bx1[tid];
    }
    const float Cs = g_C[b];

    {
        const uint4* gf = reinterpret_cast<const uint4*>(g_wfrag);
        uint4* bs = reinterpret_cast<uint4*>(smem + S_B);
#pragma unroll
        for (int j = 0; j < 4; j++) bs[tid + j * 256] = gf[tid + j * 256];
    }

    uint32_t A[2][4][4];
    {
        const float* xb = x_items + ((size_t)b * NN + (size_t)tile0) * IDM;
#pragma unroll
        for (int mt = 0; mt < 2; mt++) {
            int r0 = wid * 32 + mt * 16 + qr;
#pragma unroll
            for (int ks = 0; ks < 4; ks++) {
                int k0 = ks * 16 + qc * 2;
                float2 v00 = *reinterpret_cast<const float2*>(xb + (size_t)r0 * IDM + k0);
                float2 v10 = *reinterpret_cast<const float2*>(xb + (size_t)(r0 + 8) * IDM + k0);
                float2 v01 = *reinterpret_cast<const float2*>(xb + (size_t)r0 * IDM + k0 + 8);
                float2 v11 = *reinterpret_cast<const float2*>(xb + (size_t)(r0 + 8) * IDM + k0 + 8);
                A[mt][ks][0] = pack_h2(v00.x, v00.y);
                A[mt][ks][1] = pack_h2(v10.x, v10.y);
                A[mt][ks][2] = pack_h2(v01.x, v01.y);
                A[mt][ks][3] = pack_h2(v11.x, v11.y);
            }
        }
    }
    __syncthreads();

    float sc[2][2] = {{0.f, 0.f}, {0.f, 0.f}};
#pragma unroll 1
    for (int nt = 0; nt < 16; nt++) {
        int n0 = nt * 8 + qc * 2;
        float2 bias = *reinterpret_cast<const float2*>(&bxs[n0]);
        float2 uu   = *reinterpret_cast<const float2*>(&us[n0]);
        float c0[4] = {bias.x, bias.y, bias.x, bias.y};
        float c1[4] = {bias.x, bias.y, bias.x, bias.y};
#pragma unroll
        for (int ks = 0; ks < 4; ks++) {
            unsigned long long bb = *reinterpret_cast<const unsigned long long*>(
                smem + S_B + (((nt * 4 + ks) * 32) + lid) * 8);
            uint32_t b0 = (uint32_t)bb;
            uint32_t b1 = (uint32_t)(bb >> 32);
            mma16816(c0, A[0][ks], b0, b1);
            mma16816(c1, A[1][ks], b0, b1);
        }
        sc[0][0] += gdot(c0[0], uu.x) + gdot(c0[1], uu.y);
        sc[0][1] += gdot(c0[2], uu.x) + gdot(c0[3], uu.y);
        sc[1][0] += gdot(c1[0], uu.x) + gdot(c1[1], uu.y);
        sc[1][1] += gdot(c1[2], uu.x) + gdot(c1[3], uu.y);
    }

#pragma unroll
    for (int mt = 0; mt < 2; mt++) {
#pragma unroll
        for (int h = 0; h < 2; h++) {
            float v = sc[mt][h];
            v += __shfl_xor_sync(0xffffffffu, v, 1);
            v += __shfl_xor_sync(0xffffffffu, v, 2);
            sc[mt][h] = v;
        }
    }
    if (qc == 0) {
#pragma unroll
        for (int mt = 0; mt < 2; mt++) {
#pragma unroll
            for (int h = 0; h < 2; h++) {
                int item = tile0 + wid * 32 + mt * 16 + h * 8 + qr;
                g_scores[b * NN + item] =
                    0.08838834764831845f * (sc[mt][h] + Cs);
            }
        }
    }
}

// ---------------------------------------------------------------------------
// k3a: Michelot fixed point; z[16] register-resident; warp0 slot reduce.
// 32 blocks x 1024. Also zeroes g_gbar.
// ---------------------------------------------------------------------------
#define MICH_ROUNDS 20

__global__ void __launch_bounds__(1024) k3a_tau()
{
    __shared__ float sS[32];
    __shared__ float sK[32];
    __shared__ float sM[32];
    __shared__ float bc[1];

    const int tid  = threadIdx.x;
    const int b    = blockIdx.x;
    const int lane = tid & 31;
    const int wid  = tid >> 5;
    const float* sc = g_scores + b * NN;

    if (tid < DD) g_gbar[b * DD + tid] = 0.f;

    float z[16];
#pragma unroll
    for (int j = 0; j < 16; j++) z[j] = sc[tid + j * 1024];

    float m = z[0];
#pragma unroll
    for (int j = 1; j < 16; j++) m = fmaxf(m, z[j]);
#pragma unroll
    for (int o = 16; o > 0; o >>= 1) m = fmaxf(m, __shfl_xor_sync(0xffffffffu, m, o));
    if (lane == 0) sM[wid] = m;
    __syncthreads();
    if (wid == 0) {
        float v = sM[lane];
#pragma unroll
        for (int o = 16; o > 0; o >>= 1) v = fmaxf(v, __shfl_xor_sync(0xffffffffu, v, o));
        if (lane == 0) bc[0] = v;
    }
    __syncthreads();
    const float zmax = bc[0];

    float tau = zmax - 1.0f;
#pragma unroll 1
    for (int r = 0; r < MICH_ROUNDS; r++) {
        float s = 0.f, c = 0.f;
#pragma unroll
        for (int j = 0; j < 16; j++) {
            if (z[j] > tau) { s += z[j]; c += 1.f; }
        }
#pragma unroll
        for (int o = 16; o > 0; o >>= 1) {
            s += __shfl_xor_sync(0xffffffffu, s, o);
            c += __shfl_xor_sync(0xffffffffu, c, o);
        }
        if (lane == 0) { sS[wid] = s; sK[wid] = c; }
        __syncthreads();
        if (wid == 0) {
            float s2 = sS[lane], c2 = sK[lane];
#pragma unroll
            for (int o = 16; o > 0; o >>= 1) {
                s2 += __shfl_xor_sync(0xffffffffu, s2, o);
                c2 += __shfl_xor_sync(0xffffffffu, c2, o);
            }
            if (lane == 0) bc[0] = (s2 - 1.0f) / c2;
        }
        __syncthreads();
        float tn = bc[0];
        if (tn <= tau) break;
        tau = tn;
    }

    if (tid == 0) g_tau[b] = tau;
}

// ---------------------------------------------------------------------------
// k3b: sparse accumulation + FUSED head MLP (last block per batch).
// Grid (32, 32) x 256 threads. Reg cap: launch_bounds(256,4) => <=64 regs.
// ---------------------------------------------------------------------------
__global__ void __launch_bounds__(256, 4) k3b_accum_head(
    const float* __restrict__ x_items,
    const float* __restrict__ wx1, const float* __restrict__ bx1,
    const float* __restrict__ wx2, const float* __restrict__ bx2,
    const float* __restrict__ wvp, const float* __restrict__ bvp,
    const float* __restrict__ wp1, const float* __restrict__ bp1,
    const float* __restrict__ wp2, const float* __restrict__ bp2,
    float* __restrict__ out)
{
    __shared__ float accg[DD];
    __shared__ float buf1[DD];
    __shared__ float buf2[DD];
    __shared__ int isLast;
    const int tid  = threadIdx.x;
    const int lane = tid & 31;
    const int wid  = tid >> 5;
    const int b    = blockIdx.y;
    const int base = blockIdx.x * 512 + wid * 64;

    if (tid < DD) accg[tid] = 0.f;
    __syncthreads();

    const float tau = g_tau[b];
    const float* sc = g_scores + b * NN;

#pragma unroll 1
    for (int win = 0; win < 2; win++) {
        int idx0 = base + win * 32;
        float zz = sc[idx0 + lane];
        unsigned msk = __ballot_sync(0xffffffffu, zz > tau);
        while (msk) {
            int jb = __ffs(msk) - 1;
            msk &= msk - 1;
            float w = __shfl_sync(0xffffffffu, zz, jb) - tau;
            int item = idx0 + jb;
            const float* xr = x_items + ((size_t)b * NN + (size_t)item) * IDM;
            float x0 = xr[2 * lane], x1 = xr[2 * lane + 1];
            float a0 = bx1[lane];
            float a1 = bx1[lane + 32];
            float a2 = bx1[lane + 64];
            float a3 = bx1[lane + 96];
#pragma unroll
            for (int k = 0; k < IDM; k++) {
                float xv = __shfl_sync(0xffffffffu, (k & 1) ? x1 : x0, k >> 1);
                a0 += xv * wx1[k * DD + lane];
                a1 += xv * wx1[k * DD + lane + 32];
                a2 += xv * wx1[k * DD + lane + 64];
                a3 += xv * wx1[k * DD + lane + 96];
            }
            atomicAdd(&accg[lane],      w * gelu_exact(a0));
            atomicAdd(&accg[lane + 32], w * gelu_exact(a1));
            atomicAdd(&accg[lane + 64], w * gelu_exact(a2));
            atomicAdd(&accg[lane + 96], w * gelu_exact(a3));
        }
    }
    __syncthreads();
    if (tid < DD) {
        float v = accg[tid];
        if (v != 0.f) atomicAdd(&g_gbar[b * DD + tid], v);
    }

    // ---- fused head: last arriving block of this batch runs the MLP ----
    __threadfence();
    __syncthreads();
    if (tid == 0) {
        int old = atomicAdd(&g_cntC[b], 1);
        int last = (old == (int)gridDim.x - 1);
        if (last) g_cntC[b] = 0;       // reset for next graph replay
        isLast = last;
    }
    __syncthreads();
    if (!isLast) return;
    __threadfence();

    if (tid < DD) accg[tid] = g_gbar[b * DD + tid];
    __syncthreads();

    if (tid < DD) {
        float a0 = 0.f, a1 = 0.f;
#pragma unroll 4
        for (int k = 0; k < DD; k += 2) {
            a0 += accg[k + 0] * wx2[(k + 0) * DD + tid];
            a1 += accg[k + 1] * wx2[(k + 1) * DD + tid];
        }
        buf1[tid] = a0 + a1 + bx2[tid];
    }
    __syncthreads();
    if (tid < DD) {
        float a0 = 0.f, a1 = 0.f;
#pragma unroll 4
        for (int k = 0; k < DD; k += 2) {
            a0 += buf1[k + 0] * wvp[(k + 0) * DD + tid];
            a1 += buf1[k + 1] * wvp[(k + 1) * DD + tid];
        }
        buf2[tid] = a0 + a1 + bvp[tid];
    }
    __syncthreads();
    if (tid < DD) {
        float a0 = 0.f, a1 = 0.f;
#pragma unroll 4
        for (int k = 0; k < DD; k += 2) {
            a0 += buf2[k + 0] * wp1[(k + 0) * DD + tid];
            a1 += buf2[k + 1] * wp1[(k + 1) * DD + tid];
        }
        buf1[tid] = gelu_exact(a0 + a1 + bp1[tid]);
    }
    __syncthreads();
    if (tid < NCLS) {
        float o = bp2[tid];
#pragma unroll 4
        for (int k = 0; k < DD; k++) o += buf1[k] * wp2[k * NCLS + tid];
        out[b * NCLS + tid] = o;
    }
}

// ---------------------------------------------------------------------------
extern "C" void kernel_launch(void* const* d_in, const int* in_sizes, int n_in,
                              void* d_out, int out_size)
{
    const float* x_items = (const float*)d_in[0];
    const float* x_query = (const float*)d_in[1];
    const float* wx1 = (const float*)d_in[2];
    const float* bx1 = (const float*)d_in[3];
    const float* wx2 = (const float*)d_in[4];
    const float* bx2 = (const float*)d_in[5];
    const float* wq1 = (const float*)d_in[6];
    const float* bq1 = (const float*)d_in[7];
    const float* wq2 = (const float*)d_in[8];
    const float* bq2 = (const float*)d_in[9];
    const float* wqp = (const float*)d_in[10];
    const float* bqp = (const float*)d_in[11];
    const float* wkp = (const float*)d_in[12];
    const float* bkp = (const float*)d_in[13];
    const float* wvp = (const float*)d_in[14];
    const float* bvp = (const float*)d_in[15];
    const float* wp1 = (const float*)d_in[16];
    const float* bp1 = (const float*)d_in[17];
    const float* wp2 = (const float*)d_in[18];
    const float* bp2 = (const float*)d_in[19];
    float* out = (float*)d_out;

    cudaFuncSetAttribute(k2_scores_hmma,
                         cudaFuncAttributeMaxDynamicSharedMemorySize, S_TOT);

    k1a<<<274, 128>>>(wx1, wq2, bq2, wqp, bqp, wkp, bkp, wx2, bx2);
    k1c<<<BB, 128>>>(x_query, wq1, bq1);

    dim3 g2(NN / 256, BB);
    k2_scores_hmma<<<g2, 256, S_TOT>>>(x_items, bx1);

    k3a_tau<<<BB, 1024>>>();

    dim3 g3(32, BB);
    k3b_accum_head<<<g3, 256>>>(x_items, wx1, bx1, wx2, bx2,
                                wvp, bvp, wp1, bp1, wp2, bp2, out);
}

// round 17
// speedup vs baseline: 1.6307x; 1.1107x over previous
#include <cuda_runtime.h>
#include <cuda_fp16.h>
#include <cstdint>

#define BB   32
#define NN   16384
#define DD   128
#define IDM  64
#define NCLS 10

// ---------------------------------------------------------------------------
// Scratch (device globals — no allocation allowed)
// ---------------------------------------------------------------------------
__device__ float g_scores[BB * NN];
__device__ float g_u[BB * DD];
__device__ float g_C[BB];
__device__ float g_tau[BB];
__device__ float g_gbar[BB * DD];
__device__ __align__(16) unsigned long long g_wfrag[2048];
__device__ float g_M1[DD * DD];
__device__ float g_A2t[DD * DD];
__device__ float g_v[DD];
__device__ float g_cq[DD];
__device__ int   g_cntC[BB];   // zero-init; last user resets each replay

__device__ __forceinline__ float gelu_exact(float x) {
    return 0.5f * x * (1.0f + erff(x * 0.7071067811865475f));
}

// fp16x2 tanh-form gelu for a pair of values (score path only).
// g = 0.5x(1+tanh(0.798x + 0.0357x^3)) computed in half2; returns fp32 pair.
__device__ __forceinline__ float2 gelu2h(float xa, float xb) {
    __half2 x  = __floats2half2_rn(xa, xb);
    __half2 sq = __hmul2(x, x);
    __half2 inner = __hfma2(sq, __float2half2_rn(0.0356774081f),
                                 __float2half2_rn(0.7978845608f));
    __half2 ys = __hmul2(x, inner);
    uint32_t yu = *reinterpret_cast<uint32_t*>(&ys);
    uint32_t tu;
    asm("tanh.approx.f16x2 %0, %1;" : "=r"(tu) : "r"(yu));
    __half2 t  = *reinterpret_cast<__half2*>(&tu);
    __half2 hx = __hmul2(x, __float2half2_rn(0.5f));
    __half2 g  = __hfma2(hx, t, hx);
    return __half22float2(g);
}

__device__ __forceinline__ void mma16816(float* c, const uint32_t* a,
                                         uint32_t b0, uint32_t b1) {
    asm volatile(
        "mma.sync.aligned.m16n8k16.row.col.f32.f16.f16.f32 "
        "{%0,%1,%2,%3}, {%4,%5,%6,%7}, {%8,%9}, {%0,%1,%2,%3};"
        : "+f"(c[0]), "+f"(c[1]), "+f"(c[2]), "+f"(c[3])
        : "r"(a[0]), "r"(a[1]), "r"(a[2]), "r"(a[3]), "r"(b0), "r"(b1));
}

__device__ __forceinline__ uint32_t pack_h2(float lo, float hi) {
    __half2 h = __floats2half2_rn(lo, hi);
    return *reinterpret_cast<uint32_t*>(&h);
}

// ---------------------------------------------------------------------------
// k1a: independent precomputes. 274 blocks x 128 threads.
// ---------------------------------------------------------------------------
__global__ void __launch_bounds__(128) k1a(
    const float* __restrict__ wx1,
    const float* __restrict__ wq2, const float* __restrict__ bq2,
    const float* __restrict__ wqp, const float* __restrict__ bqp,
    const float* __restrict__ wkp, const float* __restrict__ bkp,
    const float* __restrict__ wx2, const float* __restrict__ bx2)
{
    const int bid = blockIdx.x;
    const int t   = threadIdx.x;

    if (bid < 128) {
        const int k = bid;
        float a0 = 0.f, a1 = 0.f;
#pragma unroll 8
        for (int p = 0; p < DD; p += 2) {
            a0 += wq2[k * DD + p + 0] * wqp[(p + 0) * DD + t];
            a1 += wq2[k * DD + p + 1] * wqp[(p + 1) * DD + t];
        }
        g_M1[k * DD + t] = a0 + a1;
    } else if (bid < 256) {
        const int i = bid - 128;
        float a0 = 0.f, a1 = 0.f;
#pragma unroll 8
        for (int j = 0; j < DD; j += 2) {
            a0 += wx2[i * DD + j + 0] * wkp[(j + 0) * DD + t];
            a1 += wx2[i * DD + j + 1] * wkp[(j + 1) * DD + t];
        }
        g_A2t[t * DD + i] = a0 + a1;
    } else if (bid < 272) {
        int s = (bid - 256) * 128 + t;
        int l  = s & 31;
        int ks = (s >> 5) & 3;
        int nt = s >> 7;
        int n  = nt * 8 + (l >> 2);
        int k0 = ks * 16 + (l & 3) * 2;
        float w0 = wx1[(k0 + 0) * DD + n];
        float w1 = wx1[(k0 + 1) * DD + n];
        float w8 = wx1[(k0 + 8) * DD + n];
        float w9 = wx1[(k0 + 9) * DD + n];
        g_wfrag[s] = (unsigned long long)pack_h2(w0, w1)
                   | ((unsigned long long)pack_h2(w8, w9) << 32);
    } else if (bid == 272) {
        float a = 0.f;
#pragma unroll 8
        for (int i = 0; i < DD; i++) a += bx2[i] * wkp[i * DD + t];
        g_v[t] = a + bkp[t];
    } else {
        float a = 0.f;
#pragma unroll 8
        for (int p = 0; p < DD; p++) a += bq2[p] * wqp[p * DD + t];
        g_cq[t] = a + bqp[t];
    }
}

// ---------------------------------------------------------------------------
// k1c: per-batch finals. 32 blocks x 128.
// ---------------------------------------------------------------------------
__global__ void __launch_bounds__(128) k1c(
    const float* __restrict__ xq_all,
    const float* __restrict__ wq1, const float* __restrict__ bq1)
{
    __shared__ float sg[DD];
    __shared__ float qm[DD];
    __shared__ float red[4];
    const int b = blockIdx.x;
    const int t = threadIdx.x;

    sg[t] = gelu_exact(xq_all[b] * wq1[t] + bq1[t]);
    __syncthreads();

    {
        float a0 = 0.f, a1 = 0.f;
#pragma unroll 8
        for (int k = 0; k < DD; k += 2) {
            a0 += sg[k + 0] * g_M1[(k + 0) * DD + t];
            a1 += sg[k + 1] * g_M1[(k + 1) * DD + t];
        }
        qm[t] = a0 + a1 + g_cq[t];
    }
    __syncthreads();

    {
        float a0 = 0.f, a1 = 0.f;
#pragma unroll 8
        for (int m = 0; m < DD; m += 2) {
            a0 += g_A2t[(m + 0) * DD + t] * qm[m + 0];
            a1 += g_A2t[(m + 1) * DD + t] * qm[m + 1];
        }
        g_u[b * DD + t] = a0 + a1;
    }

    float p = qm[t] * g_v[t];
#pragma unroll
    for (int o = 16; o > 0; o >>= 1) p += __shfl_xor_sync(0xffffffffu, p, o);
    if ((t & 31) == 0) red[t >> 5] = p;
    __syncthreads();
    if (t == 0) g_C[b] = red[0] + red[1] + red[2] + red[3];
}

// ---------------------------------------------------------------------------
// k2: scores via single-product fp16 HMMA; fp16x2 gelu epilogue.
// Grid (NN/256, BB), 256 threads (8 warps).
// ---------------------------------------------------------------------------
static constexpr int S_B   = 0;         // 16384 bytes
static constexpr int S_US  = 16384;
static constexpr int S_BXS = S_US + 512;
static constexpr int S_TOT = S_BXS + 512;

__global__ void __launch_bounds__(256) k2_scores_hmma(
    const float* __restrict__ x_items,
    const float* __restrict__ bx1)
{
    extern __shared__ char smem[];
    const int tid = threadIdx.x;
    const int wid = tid >> 5;
    const int lid = tid & 31;
    const int qr  = lid >> 2;
    const int qc  = lid & 3;
    const int b   = blockIdx.y;
    const int tile0 = blockIdx.x * 256;

    float* us  = reinterpret_cast<float*>(smem + S_US);
    float* bxs = reinterpret_cast<float*>(smem + S_BXS);
    if (tid < DD) {
        us[tid]  = g_u[b * DD + tid];
        bxs[tid] = bx1[tid];
    }
    const float Cs = g_C[b];

    {
        const uint4* gf = reinterpret_cast<const uint4*>(g_wfrag);
        uint4* bs = reinterpret_cast<uint4*>(smem + S_B);
#pragma unroll
        for (int j = 0; j < 4; j++) bs[tid + j * 256] = gf[tid + j * 256];
    }

    uint32_t A[2][4][4];
    {
        const float* xb = x_items + ((size_t)b * NN + (size_t)tile0) * IDM;
#pragma unroll
        for (int mt = 0; mt < 2; mt++) {
            int r0 = wid * 32 + mt * 16 + qr;
#pragma unroll
            for (int ks = 0; ks < 4; ks++) {
                int k0 = ks * 16 + qc * 2;
                float2 v00 = *reinterpret_cast<const float2*>(xb + (size_t)r0 * IDM + k0);
                float2 v10 = *reinterpret_cast<const float2*>(xb + (size_t)(r0 + 8) * IDM + k0);
                float2 v01 = *reinterpret_cast<const float2*>(xb + (size_t)r0 * IDM + k0 + 8);
                float2 v11 = *reinterpret_cast<const float2*>(xb + (size_t)(r0 + 8) * IDM + k0 + 8);
                A[mt][ks][0] = pack_h2(v00.x, v00.y);
                A[mt][ks][1] = pack_h2(v10.x, v10.y);
                A[mt][ks][2] = pack_h2(v01.x, v01.y);
                A[mt][ks][3] = pack_h2(v11.x, v11.y);
            }
        }
    }
    __syncthreads();

    float sc[2][2] = {{0.f, 0.f}, {0.f, 0.f}};
#pragma unroll 1
    for (int nt = 0; nt < 16; nt++) {
        int n0 = nt * 8 + qc * 2;
        float2 bias = *reinterpret_cast<const float2*>(&bxs[n0]);
        float2 uu   = *reinterpret_cast<const float2*>(&us[n0]);
        float c0[4] = {bias.x, bias.y, bias.x, bias.y};
        float c1[4] = {bias.x, bias.y, bias.x, bias.y};
#pragma unroll
        for (int ks = 0; ks < 4; ks++) {
            unsigned long long bb = *reinterpret_cast<const unsigned long long*>(
                smem + S_B + (((nt * 4 + ks) * 32) + lid) * 8);
            uint32_t b0 = (uint32_t)bb;
            uint32_t b1 = (uint32_t)(bb >> 32);
            mma16816(c0, A[0][ks], b0, b1);
            mma16816(c1, A[1][ks], b0, b1);
        }
        float2 g;
        g = gelu2h(c0[0], c0[1]); sc[0][0] += g.x * uu.x + g.y * uu.y;
        g = gelu2h(c0[2], c0[3]); sc[0][1] += g.x * uu.x + g.y * uu.y;
        g = gelu2h(c1[0], c1[1]); sc[1][0] += g.x * uu.x + g.y * uu.y;
        g = gelu2h(c1[2], c1[3]); sc[1][1] += g.x * uu.x + g.y * uu.y;
    }

#pragma unroll
    for (int mt = 0; mt < 2; mt++) {
#pragma unroll
        for (int h = 0; h < 2; h++) {
            float v = sc[mt][h];
            v += __shfl_xor_sync(0xffffffffu, v, 1);
            v += __shfl_xor_sync(0xffffffffu, v, 2);
            sc[mt][h] = v;
        }
    }
    if (qc == 0) {
#pragma unroll
        for (int mt = 0; mt < 2; mt++) {
#pragma unroll
            for (int h = 0; h < 2; h++) {
                int item = tile0 + wid * 32 + mt * 16 + h * 8 + qr;
                g_scores[b * NN + item] =
                    0.08838834764831845f * (sc[mt][h] + Cs);
            }
        }
    }
}

// ---------------------------------------------------------------------------
// k3a: Michelot fixed point; z[16] register-resident; warp0 slot reduce.
// 32 blocks x 1024. Also zeroes g_gbar.
// ---------------------------------------------------------------------------
#define MICH_ROUNDS 20

__global__ void __launch_bounds__(1024) k3a_tau()
{
    __shared__ float sS[32];
    __shared__ float sK[32];
    __shared__ float sM[32];
    __shared__ float bc[1];

    const int tid  = threadIdx.x;
    const int b    = blockIdx.x;
    const int lane = tid & 31;
    const int wid  = tid >> 5;
    const float* sc = g_scores + b * NN;

    if (tid < DD) g_gbar[b * DD + tid] = 0.f;

    float z[16];
#pragma unroll
    for (int j = 0; j < 16; j++) z[j] = sc[tid + j * 1024];

    float m = z[0];
#pragma unroll
    for (int j = 1; j < 16; j++) m = fmaxf(m, z[j]);
#pragma unroll
    for (int o = 16; o > 0; o >>= 1) m = fmaxf(m, __shfl_xor_sync(0xffffffffu, m, o));
    if (lane == 0) sM[wid] = m;
    __syncthreads();
    if (wid == 0) {
        float v = sM[lane];
#pragma unroll
        for (int o = 16; o > 0; o >>= 1) v = fmaxf(v, __shfl_xor_sync(0xffffffffu, v, o));
        if (lane == 0) bc[0] = v;
    }
    __syncthreads();
    const float zmax = bc[0];

    float tau = zmax - 1.0f;
#pragma unroll 1
    for (int r = 0; r < MICH_ROUNDS; r++) {
        float s = 0.f, c = 0.f;
#pragma unroll
        for (int j = 0; j < 16; j++) {
            if (z[j] > tau) { s += z[j]; c += 1.f; }
        }
#pragma unroll
        for (int o = 16; o > 0; o >>= 1) {
            s += __shfl_xor_sync(0xffffffffu, s, o);
            c += __shfl_xor_sync(0xffffffffu, c, o);
        }
        if (lane == 0) { sS[wid] = s; sK[wid] = c; }
        __syncthreads();
        if (wid == 0) {
            float s2 = sS[lane], c2 = sK[lane];
#pragma unroll
            for (int o = 16; o > 0; o >>= 1) {
                s2 += __shfl_xor_sync(0xffffffffu, s2, o);
                c2 += __shfl_xor_sync(0xffffffffu, c2, o);
            }
            if (lane == 0) bc[0] = (s2 - 1.0f) / c2;
        }
        __syncthreads();
        float tn = bc[0];
        if (tn <= tau) break;
        tau = tn;
    }

    if (tid == 0) g_tau[b] = tau;
}

// ---------------------------------------------------------------------------
// k3b: sparse accumulation (4-item batched) + fused head MLP (last block).
// Grid (32, 32) x 256 threads, reg cap (256,4) => <=64 regs.
// ---------------------------------------------------------------------------
__global__ void __launch_bounds__(256, 4) k3b_accum_head(
    const float* __restrict__ x_items,
    const float* __restrict__ wx1, const float* __restrict__ bx1,
    const float* __restrict__ wx2, const float* __restrict__ bx2,
    const float* __restrict__ wvp, const float* __restrict__ bvp,
    const float* __restrict__ wp1, const float* __restrict__ bp1,
    const float* __restrict__ wp2, const float* __restrict__ bp2,
    float* __restrict__ out)
{
    __shared__ float accg[DD];
    __shared__ float buf1[DD];
    __shared__ float buf2[DD];
    __shared__ int isLast;
    const int tid  = threadIdx.x;
    const int lane = tid & 31;
    const int wid  = tid >> 5;
    const int b    = blockIdx.y;
    const int base = blockIdx.x * 512 + wid * 64;

    if (tid < DD) accg[tid] = 0.f;
    __syncthreads();

    const float tau = g_tau[b];
    const float* sc = g_scores + b * NN;

#pragma unroll 1
    for (int win = 0; win < 2; win++) {
        int idx0 = base + win * 32;
        float zz = sc[idx0 + lane];
        unsigned msk = __ballot_sync(0xffffffffu, zz > tau);
        while (msk) {
            // pop up to 4 support items (msk is warp-uniform)
            int   jb[4];
            float wv[4];
#pragma unroll
            for (int t = 0; t < 4; t++) {
                if (msk) {
                    jb[t] = __ffs(msk) - 1;
                    msk &= msk - 1;
                    wv[t] = __shfl_sync(0xffffffffu, zz, jb[t]) - tau;
                } else {
                    jb[t] = 0;
                    wv[t] = 0.f;
                }
            }
            // load x fragments: lane l holds x[2l], x[2l+1] of each item
            float x0[4], x1[4];
#pragma unroll
            for (int t = 0; t < 4; t++) {
                const float* xr = x_items + ((size_t)b * NN + (size_t)(idx0 + jb[t])) * IDM;
                x0[t] = xr[2 * lane];
                x1[t] = xr[2 * lane + 1];
            }
            float a[4][4];
#pragma unroll
            for (int t = 0; t < 4; t++) {
                a[t][0] = bx1[lane];
                a[t][1] = bx1[lane + 32];
                a[t][2] = bx1[lane + 64];
                a[t][3] = bx1[lane + 96];
            }
#pragma unroll 4
            for (int k = 0; k < IDM; k++) {
                float w0 = wx1[k * DD + lane];
                float w1 = wx1[k * DD + lane + 32];
                float w2 = wx1[k * DD + lane + 64];
                float w3 = wx1[k * DD + lane + 96];
#pragma unroll
                for (int t = 0; t < 4; t++) {
                    float xv = __shfl_sync(0xffffffffu, (k & 1) ? x1[t] : x0[t], k >> 1);
                    a[t][0] += xv * w0;
                    a[t][1] += xv * w1;
                    a[t][2] += xv * w2;
                    a[t][3] += xv * w3;
                }
            }
#pragma unroll
            for (int t = 0; t < 4; t++) {
                if (wv[t] != 0.f) {      // uniform branch (wv from uniform msk)
                    atomicAdd(&accg[lane],      wv[t] * gelu_exact(a[t][0]));
                    atomicAdd(&accg[lane + 32], wv[t] * gelu_exact(a[t][1]));
                    atomicAdd(&accg[lane + 64], wv[t] * gelu_exact(a[t][2]));
                    atomicAdd(&accg[lane + 96], wv[t] * gelu_exact(a[t][3]));
                }
            }
        }
    }
    __syncthreads();
    if (tid < DD) {
        float v = accg[tid];
        if (v != 0.f) atomicAdd(&g_gbar[b * DD + tid], v);
    }

    // ---- fused head: last arriving block of this batch runs the MLP ----
    __threadfence();
    __syncthreads();
    if (tid == 0) {
        int old = atomicAdd(&g_cntC[b], 1);
        int last = (old == (int)gridDim.x - 1);
        if (last) g_cntC[b] = 0;       // reset for next graph replay
        isLast = last;
    }
    __syncthreads();
    if (!isLast) return;
    __threadfence();

    if (tid < DD) accg[tid] = g_gbar[b * DD + tid];
    __syncthreads();

    if (tid < DD) {
        float a0 = 0.f, a1 = 0.f;
#pragma unroll 4
        for (int k = 0; k < DD; k += 2) {
            a0 += accg[k + 0] * wx2[(k + 0) * DD + tid];
            a1 += accg[k + 1] * wx2[(k + 1) * DD + tid];
        }
        buf1[tid] = a0 + a1 + bx2[tid];
    }
    __syncthreads();
    if (tid < DD) {
        float a0 = 0.f, a1 = 0.f;
#pragma unroll 4
        for (int k = 0; k < DD; k += 2) {
            a0 += buf1[k + 0] * wvp[(k + 0) * DD + tid];
            a1 += buf1[k + 1] * wvp[(k + 1) * DD + tid];
        }
        buf2[tid] = a0 + a1 + bvp[tid];
    }
    __syncthreads();
    if (tid < DD) {
        float a0 = 0.f, a1 = 0.f;
#pragma unroll 4
        for (int k = 0; k < DD; k += 2) {
            a0 += buf2[k + 0] * wp1[(k + 0) * DD + tid];
            a1 += buf2[k + 1] * wp1[(k + 1) * DD + tid];
        }
        buf1[tid] = gelu_exact(a0 + a1 + bp1[tid]);
    }
    __syncthreads();
    if (tid < NCLS) {
        float o = bp2[tid];
#pragma unroll 4
        for (int k = 0; k < DD; k++) o += buf1[k] * wp2[k * NCLS + tid];
        out[b * NCLS + tid] = o;
    }
}

// ---------------------------------------------------------------------------
extern "C" void kernel_launch(void* const* d_in, const int* in_sizes, int n_in,
                              void* d_out, int out_size)
{
    const float* x_items = (const float*)d_in[0];
    const float* x_query = (const float*)d_in[1];
    const float* wx1 = (const float*)d_in[2];
    const float* bx1 = (const float*)d_in[3];
    const float* wx2 = (const float*)d_in[4];
    const float* bx2 = (const float*)d_in[5];
    const float* wq1 = (const float*)d_in[6];
    const float* bq1 = (const float*)d_in[7];
    const float* wq2 = (const float*)d_in[8];
    const float* bq2 = (const float*)d_in[9];
    const float* wqp = (const float*)d_in[10];
    const float* bqp = (const float*)d_in[11];
    const float* wkp = (const float*)d_in[12];
    const float* bkp = (const float*)d_in[13];
    const float* wvp = (const float*)d_in[14];
    const float* bvp = (const float*)d_in[15];
    const float* wp1 = (const float*)d_in[16];
    const float* bp1 = (const float*)d_in[17];
    const float* wp2 = (const float*)d_in[18];
    const float* bp2 = (const float*)d_in[19];
    float* out = (float*)d_out;

    cudaFuncSetAttribute(k2_scores_hmma,
                         cudaFuncAttributeMaxDynamicSharedMemorySize, S_TOT);

    k1a<<<274, 128>>>(wx1, wq2, bq2, wqp, bqp, wkp, bkp, wx2, bx2);
    k1c<<<BB, 128>>>(x_query, wq1, bq1);

    dim3 g2(NN / 256, BB);
    k2_scores_hmma<<<g2, 256, S_TOT>>>(x_items, bx1);

    k3a_tau<<<BB, 1024>>>();

    dim3 g3(32, BB);
    k3b_accum_head<<<g3, 256>>>(x_items, wx1, bx1, wx2, bx2,
                                wvp, bvp, wp1, bp1, wp2, bp2, out);
}